// round 15
// baseline (speedup 1.0000x reference)
#include <cuda_runtime.h>
#include <cuda_bf16.h>
#include <cstdint>

#define SEQ  2048
#define HID  2048
#define AKEY 1024

// ===========================================================================
// Scratch (device-global; no runtime allocation allowed)
// ===========================================================================
struct Scratch {
    __nv_bfloat16 hidden[SEQ * HID];
    __nv_bfloat16 wT[7][HID * HID];      // TRANSPOSED weights [N,K], K-major
    __nv_bfloat16 q[SEQ * HID];
    __nv_bfloat16 k[SEQ * HID];
    __nv_bfloat16 v[SEQ * HID];
    __nv_bfloat16 vT[HID * AKEY];        // v[:AKEY,:]^T  [HID][AKEY]
    __nv_bfloat16 scores[SEQ * AKEY];
    __nv_bfloat16 probs[SEQ * AKEY];
    __nv_bfloat16 ctx[SEQ * HID];
    __nv_bfloat16 post[SEQ * HID];
    __nv_bfloat16 gate[SEQ * HID];
    __nv_bfloat16 up[SEQ * HID];
    __nv_bfloat16 gated[SEQ * HID];
};
__device__ Scratch g_s;

// ===========================================================================
// PTX helpers
// ===========================================================================
__device__ __forceinline__ uint32_t smem_u32(const void* p) {
    uint32_t a;
    asm("{ .reg .u64 t; cvta.to.shared.u64 t, %1; cvt.u32.u64 %0, t; }"
        : "=r"(a) : "l"(p));
    return a;
}
__device__ __forceinline__ void cp_async16(void* smem, const void* gmem) {
    unsigned sa = smem_u32(smem);
    asm volatile("cp.async.cg.shared.global [%0], [%1], 16;\n" ::"r"(sa), "l"(gmem));
}
#define CP_COMMIT()  asm volatile("cp.async.commit_group;\n" ::: "memory")
#define CP_WAIT_N(n) asm volatile("cp.async.wait_group %0;\n" ::"n"(n) : "memory")

#define LDSM4(r, addr)                                                        \
    asm volatile("ldmatrix.sync.aligned.m8n8.x4.shared.b16 {%0,%1,%2,%3}, [%4];" \
                 : "=r"((r)[0]), "=r"((r)[1]), "=r"((r)[2]), "=r"((r)[3])     \
                 : "r"(addr))

#define MMA16816(c, a, b)                                                     \
    asm volatile("mma.sync.aligned.m16n8k16.row.col.f32.bf16.bf16.f32 "       \
                 "{%0,%1,%2,%3}, {%4,%5,%6,%7}, {%8,%9}, {%0,%1,%2,%3};"      \
                 : "+f"((c)[0]), "+f"((c)[1]), "+f"((c)[2]), "+f"((c)[3])     \
                 : "r"((a)[0]), "r"((a)[1]), "r"((a)[2]), "r"((a)[3]),        \
                   "r"((b)[0]), "r"((b)[1]))

// ===========================================================================
// mma.sync bf16 GEMM (NT): C[M,N] = A[M,K] * B[N,K]^T, both K-major (ld = K)
//   EPI=0 : C(bf16) = bf16(acc)
//   EPI=1 : C(bf16) = bf16( f32(Res) + f32(bf16(acc)) )
//   EPI=2 : C(f32)  = f32( bf16( f32(Res) + f32(bf16(acc)) ) )
// Batched over blockIdx.z: B += z*wstride, C += z*ostride.
// Block 128x128, BK=64, 3-stage cp.async, one __syncthreads per K-tile
// (32 tiles), register-double-buffered ldmatrix/MMA pipeline.
// 8 warps (2M x 4N), warp 64x32. smem rows 144B -> conflict-free.
// ===========================================================================
constexpr int BM = 128, BN = 128, BK = 64;
constexpr int NBUF   = 3;
constexpr int ROWB   = 144;                // 128B data + 16B pad
constexpr int ASTAGE = BM * ROWB;          // 18432
constexpr int BSTAGE = BN * ROWB;          // 18432
constexpr int AOFF   = 0;
constexpr int BOFF   = NBUF * ASTAGE;      // 55296
constexpr int SMEM_GEMM = NBUF * (ASTAGE + BSTAGE);   // 110592

template <int EPI>
__global__ __launch_bounds__(256, 2)
void gemm_mma(const __nv_bfloat16* __restrict__ A,
              const __nv_bfloat16* __restrict__ B,
              const __nv_bfloat16* __restrict__ Res,
              void* __restrict__ Cv,
              int K, int ldc, size_t wstride, size_t ostride) {
    extern __shared__ __align__(16) char ds[];
    const uint32_t sb = smem_u32(ds);

    const int tid  = threadIdx.x;
    const int wid  = tid >> 5;
    const int lane = tid & 31;
    const int bm = blockIdx.y * BM;
    const int bn = blockIdx.x * BN;
    const int wm = (wid & 1) * 64;         // warp M offset (2 warps over M)
    const int wn = (wid >> 1) * 32;        // warp N offset (4 warps over N)

    B += (size_t)blockIdx.z * wstride;

    // ---- tile loader: stage s <- K-tile t (BK=64 -> 8 chunks/row) --------
    auto load = [&](int t, int s) {
        const int k0 = t * BK;
        char* ab = ds + AOFF + s * ASTAGE;
        char* bb = ds + BOFF + s * BSTAGE;
#pragma unroll
        for (int v = 0; v < 4; v++) {                 // A: 1024 x 16B chunks
            int vi = tid + v * 256;
            int row = vi >> 3, ch = vi & 7;
            cp_async16(ab + row * ROWB + ch * 16,
                       A + (size_t)(bm + row) * K + k0 + ch * 8);
        }
#pragma unroll
        for (int v = 0; v < 4; v++) {                 // B: 1024 x 16B chunks
            int vi = tid + v * 256;
            int row = vi >> 3, ch = vi & 7;
            cp_async16(bb + row * ROWB + ch * 16,
                       B + (size_t)(bn + row) * K + k0 + ch * 8);
        }
        CP_COMMIT();
    };

    float acc[4][4][4];                               // [mi][nj][frag]
#pragma unroll
    for (int i = 0; i < 4; i++)
#pragma unroll
        for (int j = 0; j < 4; j++)
#pragma unroll
            for (int c = 0; c < 4; c++) acc[i][j][c] = 0.0f;

    // precomputed intra-tile ldmatrix lane addressing (byte offsets)
    const uint32_t aRowOff = (uint32_t)(lane & 15) * ROWB + ((lane >> 4) << 4);
    const uint32_t bRowSel = (uint32_t)((lane & 7) | (((lane >> 4) & 1) << 3));
    const uint32_t bChunk  = ((lane >> 3) & 1) << 4;

    uint32_t aF[2][4][4], bF[2][2][4];

    const int nt = K / BK;                // 32 or 16
    load(0, 0);
    load(1, 1);

    for (int t = 0; t < nt; t++) {
        if (t + 1 < nt) { CP_WAIT_N(1); } else { CP_WAIT_N(0); }
        __syncthreads();   // tile t visible; all warps' compute(t-1) done

        if (t + 2 < nt) load(t + 2, (t + 2) % 3);

        const uint32_t aB = sb + AOFF + (t % 3) * ASTAGE;
        const uint32_t bB = sb + BOFF + (t % 3) * BSTAGE;

        // fragment fetch for k-step ks into set s
        auto ldsm_step = [&](int ks, int s) {
#pragma unroll
            for (int i = 0; i < 4; i++)
                LDSM4(aF[s][i], aB + (uint32_t)(wm + i * 16) * ROWB + aRowOff + ks * 32);
#pragma unroll
            for (int p = 0; p < 2; p++)
                LDSM4(bF[s][p], bB + (uint32_t)(wn + p * 16 + bRowSel) * ROWB
                                   + bChunk + ks * 32);
        };

        ldsm_step(0, 0);
#pragma unroll
        for (int ks = 0; ks < 4; ks++) {              // four K=16 steps
            const int cur = ks & 1;
            if (ks < 3) ldsm_step(ks + 1, cur ^ 1);   // prefetch next fragments
#pragma unroll
            for (int i = 0; i < 4; i++)
#pragma unroll
                for (int j = 0; j < 4; j++)
                    MMA16816(acc[i][j], aF[cur][i], &bF[cur][j >> 1][(j & 1) * 2]);
        }
        // top-of-next-iteration barrier orders buffer reuse
    }

    // ---- fused epilogue (direct fragment-indexed stores) -----------------
    __nv_bfloat16* Cb = reinterpret_cast<__nv_bfloat16*>(Cv) + (size_t)blockIdx.z * ostride;
    float*         Cf = reinterpret_cast<float*>(Cv);
    const int er = lane >> 2;            // 0..7
    const int ec = (lane & 3) * 2;       // 0,2,4,6

#pragma unroll
    for (int i = 0; i < 4; i++) {
#pragma unroll
        for (int j = 0; j < 4; j++) {
            const int gcol = bn + wn + j * 8 + ec;
#pragma unroll
            for (int h = 0; h < 2; h++) {             // rows er and er+8
                const int grow = bm + wm + i * 16 + er + h * 8;
                const size_t base = (size_t)grow * ldc + gcol;
                float x0 = acc[i][j][2 * h], x1 = acc[i][j][2 * h + 1];
                __nv_bfloat162 t2 = __floats2bfloat162_rn(x0, x1);
                if constexpr (EPI == 0) {
                    *reinterpret_cast<__nv_bfloat162*>(Cb + base) = t2;
                } else {
                    __nv_bfloat162 r2 = *reinterpret_cast<const __nv_bfloat162*>(Res + base);
                    float ox = __bfloat162float(r2.x) + __bfloat162float(t2.x);
                    float oy = __bfloat162float(r2.y) + __bfloat162float(t2.y);
                    __nv_bfloat162 ob = __floats2bfloat162_rn(ox, oy);
                    if constexpr (EPI == 1) {
                        *reinterpret_cast<__nv_bfloat162*>(Cb + base) = ob;
                    } else {
                        float2 of;
                        of.x = __bfloat162float(ob.x);
                        of.y = __bfloat162float(ob.y);
                        *reinterpret_cast<float2*>(Cf + base) = of;
                    }
                }
            }
        }
    }
}

// ===========================================================================
// Input conversion / transposes
// ===========================================================================
__global__ void cvt_hidden_kernel(const float* __restrict__ s, int n4) {
    const float4* src = reinterpret_cast<const float4*>(s);
    __nv_bfloat162* dst = reinterpret_cast<__nv_bfloat162*>(g_s.hidden);
    for (int i = blockIdx.x * blockDim.x + threadIdx.x; i < n4;
         i += gridDim.x * blockDim.x) {
        float4 v = src[i];
        dst[2 * i]     = __floats2bfloat162_rn(v.x, v.y);
        dst[2 * i + 1] = __floats2bfloat162_rn(v.z, v.w);
    }
}

struct TPack { const float* s[7]; };

// wT[z][n*HID + k] = bf16(W[z][k*HID + n])
// 64x64 tiles, float4-vectorized loads, 16B-vector bf16 stores.
__global__ void transpose_w_kernel(TPack p) {
    __shared__ float tile[64][65];
    const float* src = p.s[blockIdx.z];
    __nv_bfloat16* dst = g_s.wT[blockIdx.z];
    const int tid = threadIdx.x;                    // 256 threads
    const int k0 = blockIdx.y * 64;                 // source row base (k)
    const int n0 = blockIdx.x * 64;                 // source col base (n)

#pragma unroll
    for (int v = 0; v < 4; v++) {
        int idx = tid + v * 256;
        int r = idx >> 4, c4 = idx & 15;
        float4 f = *reinterpret_cast<const float4*>(
            src + (size_t)(k0 + r) * HID + n0 + c4 * 4);
        tile[r][c4 * 4 + 0] = f.x;
        tile[r][c4 * 4 + 1] = f.y;
        tile[r][c4 * 4 + 2] = f.z;
        tile[r][c4 * 4 + 3] = f.w;
    }
    __syncthreads();

#pragma unroll
    for (int v = 0; v < 2; v++) {
        int idx = tid + v * 256;
        int n = idx >> 3, seg = idx & 7;
        __nv_bfloat162 o[4];
#pragma unroll
        for (int j = 0; j < 4; j++)
            o[j] = __floats2bfloat162_rn(tile[seg * 8 + 2 * j][n],
                                         tile[seg * 8 + 2 * j + 1][n]);
        *reinterpret_cast<uint4*>(dst + (size_t)(n0 + n) * HID + k0 + seg * 8) =
            *reinterpret_cast<uint4*>(o);
    }
}

// vT[h*AKEY + s] = v[s*HID + h]   (s < AKEY)
__global__ void transpose_v_kernel() {
    __shared__ __nv_bfloat16 tile[32][33];
    const int x  = blockIdx.x * 32 + threadIdx.x;   // h
    const int y0 = blockIdx.y * 32;                 // s base
#pragma unroll
    for (int j = 0; j < 32; j += 8)
        tile[threadIdx.y + j][threadIdx.x] =
            g_s.v[(size_t)(y0 + threadIdx.y + j) * HID + x];
    __syncthreads();
    const int h = blockIdx.x * 32 + threadIdx.y;
    const int s = y0 + threadIdx.x;
#pragma unroll
    for (int j = 0; j < 32; j += 8)
        g_s.vT[(size_t)(h + j) * AKEY + s] = tile[threadIdx.x][threadIdx.y + j];
}

// ===========================================================================
// Softmax (reference rounding) — shuffle reductions, 2 barriers
// ===========================================================================
__global__ void softmax_kernel(const __nv_bfloat16* __restrict__ sc,
                               __nv_bfloat16* __restrict__ pr) {
    const int row = blockIdx.x;
    const int tid = threadIdx.x;
    const int wid = tid >> 5;
    const int lane = tid & 31;
    const float scale = 0.022097086912079608f;  // 1/sqrt(2048)
    __shared__ float shm[8], shs[8];

    float x[4];
#pragma unroll
    for (int i = 0; i < 4; i++) {
        float vraw = __bfloat162float(sc[(size_t)row * AKEY + tid + i * 256]) * scale;
        x[i] = __bfloat162float(__float2bfloat16(vraw));
    }
    float m = fmaxf(fmaxf(x[0], x[1]), fmaxf(x[2], x[3]));
#pragma unroll
    for (int off = 16; off > 0; off >>= 1)
        m = fmaxf(m, __shfl_xor_sync(0xFFFFFFFFu, m, off));
    if (lane == 0) shm[wid] = m;
    __syncthreads();
    float mall = shm[0];
#pragma unroll
    for (int w = 1; w < 8; w++) mall = fmaxf(mall, shm[w]);

    float e[4]; float sum = 0.f;
#pragma unroll
    for (int i = 0; i < 4; i++) { e[i] = expf(x[i] - mall); sum += e[i]; }
#pragma unroll
    for (int off = 16; off > 0; off >>= 1)
        sum += __shfl_xor_sync(0xFFFFFFFFu, sum, off);
    if (lane == 0) shs[wid] = sum;
    __syncthreads();
    float tot = 0.f;
#pragma unroll
    for (int w = 0; w < 8; w++) tot += shs[w];

#pragma unroll
    for (int i = 0; i < 4; i++)
        pr[(size_t)row * AKEY + tid + i * 256] = __float2bfloat16(e[i] / tot);
}

// ===========================================================================
// gated = bf16( f32(bf16(gelu_tanh(f32(gate)))) * f32(up) )
// ===========================================================================
__global__ void gelu_mul_kernel(const __nv_bfloat16* __restrict__ g,
                                const __nv_bfloat16* __restrict__ u,
                                __nv_bfloat16* __restrict__ o, int n2) {
    for (int i = blockIdx.x * blockDim.x + threadIdx.x; i < n2;
         i += gridDim.x * blockDim.x) {
        __nv_bfloat162 gv = reinterpret_cast<const __nv_bfloat162*>(g)[i];
        __nv_bfloat162 uv = reinterpret_cast<const __nv_bfloat162*>(u)[i];
        float xs[2] = {__bfloat162float(gv.x), __bfloat162float(gv.y)};
        float us[2] = {__bfloat162float(uv.x), __bfloat162float(uv.y)};
        float os[2];
#pragma unroll
        for (int c = 0; c < 2; c++) {
            float x = xs[c];
            float t = tanhf(0.7978845608028654f * (x + 0.044715f * x * x * x));
            float act = 0.5f * x * (1.0f + t);
            float ab = __bfloat162float(__float2bfloat16(act));
            os[c] = ab * us[c];
        }
        reinterpret_cast<__nv_bfloat162*>(o)[i] = __floats2bfloat162_rn(os[0], os[1]);
    }
}

// ===========================================================================
// kernel_launch
// ===========================================================================
extern "C" void kernel_launch(void* const* d_in, const int* in_sizes, int n_in,
                              void* d_out, int out_size) {
    Scratch* S;
    cudaGetSymbolAddress((void**)&S, g_s);

    cudaFuncSetAttribute(gemm_mma<0>, cudaFuncAttributeMaxDynamicSharedMemorySize, SMEM_GEMM);
    cudaFuncSetAttribute(gemm_mma<1>, cudaFuncAttributeMaxDynamicSharedMemorySize, SMEM_GEMM);
    cudaFuncSetAttribute(gemm_mma<2>, cudaFuncAttributeMaxDynamicSharedMemorySize, SMEM_GEMM);

    // input order: hidden, q_proj, k_proj, v_proj, o_proj, gate_proj, up_proj, down_proj
    cvt_hidden_kernel<<<256, 256>>>((const float*)d_in[0], SEQ * HID / 4);
    TPack tp;
    for (int i = 0; i < 7; i++) tp.s[i] = (const float*)d_in[i + 1];
    transpose_w_kernel<<<dim3(32, 32, 7), 256>>>(tp);

    const size_t WS = (size_t)HID * HID;
    const size_t OS = (size_t)SEQ * HID;
    const dim3 blk(256);

    // q,k,v = hidden @ W^T  (batched z=3)
    gemm_mma<0><<<dim3(HID / BN, SEQ / BM, 3), blk, SMEM_GEMM>>>(
        S->hidden, S->wT[0], nullptr, S->q, HID, HID, WS, OS);

    // vT = v[:AKEY,:]^T
    transpose_v_kernel<<<dim3(HID / 32, AKEY / 32), dim3(32, 8)>>>();

    // scores = q @ k[:AKEY]^T  (NT natural)
    gemm_mma<0><<<dim3(AKEY / BN, SEQ / BM, 1), blk, SMEM_GEMM>>>(
        S->q, S->k, nullptr, S->scores, HID, AKEY, 0, 0);

    softmax_kernel<<<SEQ, 256>>>(S->scores, S->probs);

    // context = probs @ v[:AKEY]  (B = vT [HID][AKEY])
    gemm_mma<0><<<dim3(HID / BN, SEQ / BM, 1), blk, SMEM_GEMM>>>(
        S->probs, S->vT, nullptr, S->ctx, AKEY, HID, 0, 0);

    // post = bf16(f32(hidden) + f32(bf16(ctx @ o_proj)))
    gemm_mma<1><<<dim3(HID / BN, SEQ / BM, 1), blk, SMEM_GEMM>>>(
        S->ctx, S->wT[3], S->hidden, S->post, HID, HID, 0, 0);

    // gate,up = post @ {gate,up}^T  (batched z=2)
    gemm_mma<0><<<dim3(HID / BN, SEQ / BM, 2), blk, SMEM_GEMM>>>(
        S->post, S->wT[4], nullptr, S->gate, HID, HID, WS, OS);

    gelu_mul_kernel<<<2048, 256>>>(S->gate, S->up, S->gated, SEQ * HID / 2);

    // out(f32) = f32(bf16(f32(post) + f32(bf16(gated @ down^T))))
    gemm_mma<2><<<dim3(HID / BN, SEQ / BM, 1), blk, SMEM_GEMM>>>(
        S->gated, S->wT[6], S->post, d_out, HID, HID, 0, 0);
}

// round 16
// speedup vs baseline: 1.6296x; 1.6296x over previous
#include <cuda_runtime.h>
#include <cuda_bf16.h>
#include <cstdint>

#define SEQ  2048
#define HID  2048
#define AKEY 1024

// ===========================================================================
// Scratch (device-global; no runtime allocation allowed)
// ===========================================================================
struct Scratch {
    __nv_bfloat16 hidden[SEQ * HID];
    __nv_bfloat16 wT[7][HID * HID];      // TRANSPOSED weights [N,K], K-major
    __nv_bfloat16 q[SEQ * HID];
    __nv_bfloat16 k[SEQ * HID];
    __nv_bfloat16 v[SEQ * HID];
    __nv_bfloat16 vT[HID * AKEY];        // v[:AKEY,:]^T  [HID][AKEY]
    __nv_bfloat16 scores[SEQ * AKEY];
    __nv_bfloat16 probs[SEQ * AKEY];
    __nv_bfloat16 ctx[SEQ * HID];
    __nv_bfloat16 post[SEQ * HID];
    __nv_bfloat16 gate[SEQ * HID];
    __nv_bfloat16 up[SEQ * HID];
    __nv_bfloat16 gated[SEQ * HID];
};
__device__ Scratch g_s;

// ===========================================================================
// PTX helpers
// ===========================================================================
__device__ __forceinline__ uint32_t smem_u32(const void* p) {
    uint32_t a;
    asm("{ .reg .u64 t; cvta.to.shared.u64 t, %1; cvt.u32.u64 %0, t; }"
        : "=r"(a) : "l"(p));
    return a;
}
__device__ __forceinline__ void cp_async16(void* smem, const void* gmem) {
    unsigned sa = smem_u32(smem);
    asm volatile("cp.async.cg.shared.global [%0], [%1], 16;\n" ::"r"(sa), "l"(gmem));
}
#define CP_COMMIT()  asm volatile("cp.async.commit_group;\n" ::: "memory")
#define CP_WAIT_N(n) asm volatile("cp.async.wait_group %0;\n" ::"n"(n) : "memory")

#define LDSM4(r, addr)                                                        \
    asm volatile("ldmatrix.sync.aligned.m8n8.x4.shared.b16 {%0,%1,%2,%3}, [%4];" \
                 : "=r"((r)[0]), "=r"((r)[1]), "=r"((r)[2]), "=r"((r)[3])     \
                 : "r"(addr))

#define MMA16816(c, a, b)                                                     \
    asm volatile("mma.sync.aligned.m16n8k16.row.col.f32.bf16.bf16.f32 "       \
                 "{%0,%1,%2,%3}, {%4,%5,%6,%7}, {%8,%9}, {%0,%1,%2,%3};"      \
                 : "+f"((c)[0]), "+f"((c)[1]), "+f"((c)[2]), "+f"((c)[3])     \
                 : "r"((a)[0]), "r"((a)[1]), "r"((a)[2]), "r"((a)[3]),        \
                   "r"((b)[0]), "r"((b)[1]))

// ===========================================================================
// mma.sync bf16 GEMM (NT): C[M,N] = A[M,K] * B[N,K]^T, both K-major (ld = K)
//   EPI=0 : C(bf16) = bf16(acc)
//   EPI=1 : C(bf16) = bf16( f32(Res) + f32(bf16(acc)) )
//   EPI=2 : C(f32)  = f32( bf16( f32(Res) + f32(bf16(acc)) ) )
// Batched over blockIdx.z: B += z*wstride, C += z*ostride.
// Block 128x128, BK=32, 4-stage cp.async (wait_group 2 steady state),
// ONE __syncthreads per K-tile. 8 warps (2M x 4N), warp 64x32.
// smem rows padded to 80B -> conflict-free ldmatrix.
// (Round-14 proven structure: single fragment set, no reg double-buffering —
//  at 64 acc regs there is no register headroom for pipelined fragments.)
// ===========================================================================
constexpr int BM = 128, BN = 128, BK = 32;
constexpr int NBUF   = 4;
constexpr int ROWB   = 80;                 // bytes per padded smem row
constexpr int ASTAGE = BM * ROWB;          // 10240
constexpr int BSTAGE = BN * ROWB;          // 10240
constexpr int AOFF   = 0;
constexpr int BOFF   = NBUF * ASTAGE;      // 40960
constexpr int SMEM_GEMM = NBUF * (ASTAGE + BSTAGE);   // 81920

template <int EPI>
__global__ __launch_bounds__(256, 2)
void gemm_mma(const __nv_bfloat16* __restrict__ A,
              const __nv_bfloat16* __restrict__ B,
              const __nv_bfloat16* __restrict__ Res,
              void* __restrict__ Cv,
              int K, int ldc, size_t wstride, size_t ostride) {
    extern __shared__ __align__(16) char ds[];
    const uint32_t sb = smem_u32(ds);

    const int tid  = threadIdx.x;
    const int wid  = tid >> 5;
    const int lane = tid & 31;
    const int bm = blockIdx.y * BM;
    const int bn = blockIdx.x * BN;
    const int wm = (wid & 1) * 64;         // warp M offset (2 warps over M)
    const int wn = (wid >> 1) * 32;        // warp N offset (4 warps over N)

    B += (size_t)blockIdx.z * wstride;

    // ---- tile loader: stage s <- K-tile t -------------------------------
    auto load = [&](int t, int s) {
        const int k0 = t * BK;
        char* ab = ds + AOFF + s * ASTAGE;
        char* bb = ds + BOFF + s * BSTAGE;
#pragma unroll
        for (int v = 0; v < 2; v++) {                 // A: 512 x 16B chunks
            int vi = tid + v * 256;
            int row = vi >> 2, ch = vi & 3;
            cp_async16(ab + row * ROWB + ch * 16,
                       A + (size_t)(bm + row) * K + k0 + ch * 8);
        }
#pragma unroll
        for (int v = 0; v < 2; v++) {                 // B: 512 x 16B chunks
            int vi = tid + v * 256;
            int row = vi >> 2, ch = vi & 3;
            cp_async16(bb + row * ROWB + ch * 16,
                       B + (size_t)(bn + row) * K + k0 + ch * 8);
        }
        CP_COMMIT();
    };

    float acc[4][4][4];                               // [mi][nj][frag]
#pragma unroll
    for (int i = 0; i < 4; i++)
#pragma unroll
        for (int j = 0; j < 4; j++)
#pragma unroll
            for (int c = 0; c < 4; c++) acc[i][j][c] = 0.0f;

    const int nt = K / BK;
    load(0, 0);
    load(1, 1);
    load(2, 2);

    for (int t = 0; t < nt; t++) {
        const int rem = nt - 1 - t;
        if (rem >= 2)      { CP_WAIT_N(2); }
        else if (rem == 1) { CP_WAIT_N(1); }
        else               { CP_WAIT_N(0); }
        __syncthreads();   // tile t visible; all warps' compute(t-1) done

        if (t + 3 < nt) load(t + 3, (t + 3) & 3);

        const int buf = t & 3;
        const uint32_t aB = sb + AOFF + buf * ASTAGE;
        const uint32_t bB = sb + BOFF + buf * BSTAGE;

#pragma unroll
        for (int ks = 0; ks < 2; ks++) {              // two K=16 steps
            uint32_t aF[4][4], bF[2][4];
#pragma unroll
            for (int i = 0; i < 4; i++) {
                uint32_t addr = aB + (uint32_t)(wm + i * 16 + (lane & 15)) * ROWB
                              + ks * 32 + ((lane >> 4) << 4);
                LDSM4(aF[i], addr);
            }
#pragma unroll
            for (int p = 0; p < 2; p++) {
                uint32_t row = wn + p * 16 + ((lane & 7) | (((lane >> 4) & 1) << 3));
                uint32_t addr = bB + row * ROWB + ks * 32 + (((lane >> 3) & 1) << 4);
                LDSM4(bF[p], addr);
            }
#pragma unroll
            for (int i = 0; i < 4; i++)
#pragma unroll
                for (int j = 0; j < 4; j++)
                    MMA16816(acc[i][j], aF[i], &bF[j >> 1][(j & 1) * 2]);
        }
        // top-of-next-iteration barrier orders buffer reuse
    }

    // ---- fused epilogue (direct fragment-indexed stores) -----------------
    __nv_bfloat16* Cb = reinterpret_cast<__nv_bfloat16*>(Cv) + (size_t)blockIdx.z * ostride;
    float*         Cf = reinterpret_cast<float*>(Cv);
    const int er = lane >> 2;            // 0..7
    const int ec = (lane & 3) * 2;       // 0,2,4,6

#pragma unroll
    for (int i = 0; i < 4; i++) {
#pragma unroll
        for (int j = 0; j < 4; j++) {
            const int gcol = bn + wn + j * 8 + ec;
#pragma unroll
            for (int h = 0; h < 2; h++) {             // rows er and er+8
                const int grow = bm + wm + i * 16 + er + h * 8;
                const size_t base = (size_t)grow * ldc + gcol;
                float x0 = acc[i][j][2 * h], x1 = acc[i][j][2 * h + 1];
                __nv_bfloat162 t2 = __floats2bfloat162_rn(x0, x1);
                if constexpr (EPI == 0) {
                    *reinterpret_cast<__nv_bfloat162*>(Cb + base) = t2;
                } else {
                    __nv_bfloat162 r2 = *reinterpret_cast<const __nv_bfloat162*>(Res + base);
                    float ox = __bfloat162float(r2.x) + __bfloat162float(t2.x);
                    float oy = __bfloat162float(r2.y) + __bfloat162float(t2.y);
                    __nv_bfloat162 ob = __floats2bfloat162_rn(ox, oy);
                    if constexpr (EPI == 1) {
                        *reinterpret_cast<__nv_bfloat162*>(Cb + base) = ob;
                    } else {
                        float2 of;
                        of.x = __bfloat162float(ob.x);
                        of.y = __bfloat162float(ob.y);
                        *reinterpret_cast<float2*>(Cf + base) = of;
                    }
                }
            }
        }
    }
}

// ===========================================================================
// Input conversion / transposes
// ===========================================================================
__global__ void cvt_hidden_kernel(const float* __restrict__ s, int n4) {
    const float4* src = reinterpret_cast<const float4*>(s);
    __nv_bfloat162* dst = reinterpret_cast<__nv_bfloat162*>(g_s.hidden);
    for (int i = blockIdx.x * blockDim.x + threadIdx.x; i < n4;
         i += gridDim.x * blockDim.x) {
        float4 v = src[i];
        dst[2 * i]     = __floats2bfloat162_rn(v.x, v.y);
        dst[2 * i + 1] = __floats2bfloat162_rn(v.z, v.w);
    }
}

struct TPack { const float* s[7]; };

// wT[z][n*HID + k] = bf16(W[z][k*HID + n])
// 64x64 tiles, float4-vectorized loads, 16B-vector bf16 stores.
__global__ void transpose_w_kernel(TPack p) {
    __shared__ float tile[64][65];
    const float* src = p.s[blockIdx.z];
    __nv_bfloat16* dst = g_s.wT[blockIdx.z];
    const int tid = threadIdx.x;                    // 256 threads
    const int k0 = blockIdx.y * 64;                 // source row base (k)
    const int n0 = blockIdx.x * 64;                 // source col base (n)

#pragma unroll
    for (int v = 0; v < 4; v++) {
        int idx = tid + v * 256;
        int r = idx >> 4, c4 = idx & 15;
        float4 f = *reinterpret_cast<const float4*>(
            src + (size_t)(k0 + r) * HID + n0 + c4 * 4);
        tile[r][c4 * 4 + 0] = f.x;
        tile[r][c4 * 4 + 1] = f.y;
        tile[r][c4 * 4 + 2] = f.z;
        tile[r][c4 * 4 + 3] = f.w;
    }
    __syncthreads();

#pragma unroll
    for (int v = 0; v < 2; v++) {
        int idx = tid + v * 256;
        int n = idx >> 3, seg = idx & 7;
        __nv_bfloat162 o[4];
#pragma unroll
        for (int j = 0; j < 4; j++)
            o[j] = __floats2bfloat162_rn(tile[seg * 8 + 2 * j][n],
                                         tile[seg * 8 + 2 * j + 1][n]);
        *reinterpret_cast<uint4*>(dst + (size_t)(n0 + n) * HID + k0 + seg * 8) =
            *reinterpret_cast<uint4*>(o);
    }
}

// vT[h*AKEY + s] = v[s*HID + h]   (s < AKEY)
__global__ void transpose_v_kernel() {
    __shared__ __nv_bfloat16 tile[32][33];
    const int x  = blockIdx.x * 32 + threadIdx.x;   // h
    const int y0 = blockIdx.y * 32;                 // s base
#pragma unroll
    for (int j = 0; j < 32; j += 8)
        tile[threadIdx.y + j][threadIdx.x] =
            g_s.v[(size_t)(y0 + threadIdx.y + j) * HID + x];
    __syncthreads();
    const int h = blockIdx.x * 32 + threadIdx.y;
    const int s = y0 + threadIdx.x;
#pragma unroll
    for (int j = 0; j < 32; j += 8)
        g_s.vT[(size_t)(h + j) * AKEY + s] = tile[threadIdx.x][threadIdx.y + j];
}

// ===========================================================================
// Softmax (reference rounding) — shuffle reductions, 2 barriers
// ===========================================================================
__global__ void softmax_kernel(const __nv_bfloat16* __restrict__ sc,
                               __nv_bfloat16* __restrict__ pr) {
    const int row = blockIdx.x;
    const int tid = threadIdx.x;
    const int wid = tid >> 5;
    const int lane = tid & 31;
    const float scale = 0.022097086912079608f;  // 1/sqrt(2048)
    __shared__ float shm[8], shs[8];

    float x[4];
#pragma unroll
    for (int i = 0; i < 4; i++) {
        float vraw = __bfloat162float(sc[(size_t)row * AKEY + tid + i * 256]) * scale;
        x[i] = __bfloat162float(__float2bfloat16(vraw));
    }
    float m = fmaxf(fmaxf(x[0], x[1]), fmaxf(x[2], x[3]));
#pragma unroll
    for (int off = 16; off > 0; off >>= 1)
        m = fmaxf(m, __shfl_xor_sync(0xFFFFFFFFu, m, off));
    if (lane == 0) shm[wid] = m;
    __syncthreads();
    float mall = shm[0];
#pragma unroll
    for (int w = 1; w < 8; w++) mall = fmaxf(mall, shm[w]);

    float e[4]; float sum = 0.f;
#pragma unroll
    for (int i = 0; i < 4; i++) { e[i] = expf(x[i] - mall); sum += e[i]; }
#pragma unroll
    for (int off = 16; off > 0; off >>= 1)
        sum += __shfl_xor_sync(0xFFFFFFFFu, sum, off);
    if (lane == 0) shs[wid] = sum;
    __syncthreads();
    float tot = 0.f;
#pragma unroll
    for (int w = 0; w < 8; w++) tot += shs[w];

#pragma unroll
    for (int i = 0; i < 4; i++)
        pr[(size_t)row * AKEY + tid + i * 256] = __float2bfloat16(e[i] / tot);
}

// ===========================================================================
// gated = bf16( f32(bf16(gelu_tanh(f32(gate)))) * f32(up) )
// ===========================================================================
__global__ void gelu_mul_kernel(const __nv_bfloat16* __restrict__ g,
                                const __nv_bfloat16* __restrict__ u,
                                __nv_bfloat16* __restrict__ o, int n2) {
    for (int i = blockIdx.x * blockDim.x + threadIdx.x; i < n2;
         i += gridDim.x * blockDim.x) {
        __nv_bfloat162 gv = reinterpret_cast<const __nv_bfloat162*>(g)[i];
        __nv_bfloat162 uv = reinterpret_cast<const __nv_bfloat162*>(u)[i];
        float xs[2] = {__bfloat162float(gv.x), __bfloat162float(gv.y)};
        float us[2] = {__bfloat162float(uv.x), __bfloat162float(uv.y)};
        float os[2];
#pragma unroll
        for (int c = 0; c < 2; c++) {
            float x = xs[c];
            float t = tanhf(0.7978845608028654f * (x + 0.044715f * x * x * x));
            float act = 0.5f * x * (1.0f + t);
            float ab = __bfloat162float(__float2bfloat16(act));
            os[c] = ab * us[c];
        }
        reinterpret_cast<__nv_bfloat162*>(o)[i] = __floats2bfloat162_rn(os[0], os[1]);
    }
}

// ===========================================================================
// kernel_launch
// ===========================================================================
extern "C" void kernel_launch(void* const* d_in, const int* in_sizes, int n_in,
                              void* d_out, int out_size) {
    Scratch* S;
    cudaGetSymbolAddress((void**)&S, g_s);

    cudaFuncSetAttribute(gemm_mma<0>, cudaFuncAttributeMaxDynamicSharedMemorySize, SMEM_GEMM);
    cudaFuncSetAttribute(gemm_mma<1>, cudaFuncAttributeMaxDynamicSharedMemorySize, SMEM_GEMM);
    cudaFuncSetAttribute(gemm_mma<2>, cudaFuncAttributeMaxDynamicSharedMemorySize, SMEM_GEMM);

    // input order: hidden, q_proj, k_proj, v_proj, o_proj, gate_proj, up_proj, down_proj
    cvt_hidden_kernel<<<256, 256>>>((const float*)d_in[0], SEQ * HID / 4);
    TPack tp;
    for (int i = 0; i < 7; i++) tp.s[i] = (const float*)d_in[i + 1];
    transpose_w_kernel<<<dim3(32, 32, 7), 256>>>(tp);

    const size_t WS = (size_t)HID * HID;
    const size_t OS = (size_t)SEQ * HID;
    const dim3 blk(256);

    // q,k,v = hidden @ W^T  (batched z=3)
    gemm_mma<0><<<dim3(HID / BN, SEQ / BM, 3), blk, SMEM_GEMM>>>(
        S->hidden, S->wT[0], nullptr, S->q, HID, HID, WS, OS);

    // vT = v[:AKEY,:]^T
    transpose_v_kernel<<<dim3(HID / 32, AKEY / 32), dim3(32, 8)>>>();

    // scores = q @ k[:AKEY]^T  (NT natural)
    gemm_mma<0><<<dim3(AKEY / BN, SEQ / BM, 1), blk, SMEM_GEMM>>>(
        S->q, S->k, nullptr, S->scores, HID, AKEY, 0, 0);

    softmax_kernel<<<SEQ, 256>>>(S->scores, S->probs);

    // context = probs @ v[:AKEY]  (B = vT [HID][AKEY])
    gemm_mma<0><<<dim3(HID / BN, SEQ / BM, 1), blk, SMEM_GEMM>>>(
        S->probs, S->vT, nullptr, S->ctx, AKEY, HID, 0, 0);

    // post = bf16(f32(hidden) + f32(bf16(ctx @ o_proj)))
    gemm_mma<1><<<dim3(HID / BN, SEQ / BM, 1), blk, SMEM_GEMM>>>(
        S->ctx, S->wT[3], S->hidden, S->post, HID, HID, 0, 0);

    // gate,up = post @ {gate,up}^T  (batched z=2)
    gemm_mma<0><<<dim3(HID / BN, SEQ / BM, 2), blk, SMEM_GEMM>>>(
        S->post, S->wT[4], nullptr, S->gate, HID, HID, WS, OS);

    gelu_mul_kernel<<<2048, 256>>>(S->gate, S->up, S->gated, SEQ * HID / 2);

    // out(f32) = f32(bf16(f32(post) + f32(bf16(gated @ down^T))))
    gemm_mma<2><<<dim3(HID / BN, SEQ / BM, 1), blk, SMEM_GEMM>>>(
        S->gated, S->wT[6], S->post, d_out, HID, HID, 0, 0);
}

// round 17
// speedup vs baseline: 1.8086x; 1.1099x over previous
#include <cuda_runtime.h>
#include <cuda_bf16.h>
#include <cstdint>

#define SEQ  2048
#define HID  2048
#define AKEY 1024

// ===========================================================================
// Scratch (device-global; no runtime allocation allowed)
// ===========================================================================
struct Scratch {
    __nv_bfloat16 hidden[SEQ * HID];
    __nv_bfloat16 wT[7][HID * HID];      // TRANSPOSED weights [N,K], K-major
    __nv_bfloat16 q[SEQ * HID];
    __nv_bfloat16 k[SEQ * HID];
    __nv_bfloat16 v[SEQ * HID];
    __nv_bfloat16 vT[HID * AKEY];        // v[:AKEY,:]^T  [HID][AKEY]
    __nv_bfloat16 scores[SEQ * AKEY];
    __nv_bfloat16 probs[SEQ * AKEY];
    __nv_bfloat16 ctx[SEQ * HID];
    __nv_bfloat16 post[SEQ * HID];
    __nv_bfloat16 gate[SEQ * HID];
    __nv_bfloat16 up[SEQ * HID];
    __nv_bfloat16 gated[SEQ * HID];
};
__device__ Scratch g_s;

// ===========================================================================
// PTX helpers
// ===========================================================================
__device__ __forceinline__ uint32_t smem_u32(const void* p) {
    uint32_t a;
    asm("{ .reg .u64 t; cvta.to.shared.u64 t, %1; cvt.u32.u64 %0, t; }"
        : "=r"(a) : "l"(p));
    return a;
}
__device__ __forceinline__ void cp_async16(void* smem, const void* gmem) {
    unsigned sa = smem_u32(smem);
    asm volatile("cp.async.cg.shared.global [%0], [%1], 16;\n" ::"r"(sa), "l"(gmem));
}
#define CP_COMMIT()  asm volatile("cp.async.commit_group;\n" ::: "memory")
#define CP_WAIT_N(n) asm volatile("cp.async.wait_group %0;\n" ::"n"(n) : "memory")

#define LDSM4(r, addr)                                                        \
    asm volatile("ldmatrix.sync.aligned.m8n8.x4.shared.b16 {%0,%1,%2,%3}, [%4];" \
                 : "=r"((r)[0]), "=r"((r)[1]), "=r"((r)[2]), "=r"((r)[3])     \
                 : "r"(addr))

#define MMA16816(c, a, b)                                                     \
    asm volatile("mma.sync.aligned.m16n8k16.row.col.f32.bf16.bf16.f32 "       \
                 "{%0,%1,%2,%3}, {%4,%5,%6,%7}, {%8,%9}, {%0,%1,%2,%3};"      \
                 : "+f"((c)[0]), "+f"((c)[1]), "+f"((c)[2]), "+f"((c)[3])     \
                 : "r"((a)[0]), "r"((a)[1]), "r"((a)[2]), "r"((a)[3]),        \
                   "r"((b)[0]), "r"((b)[1]))

// ===========================================================================
// mma.sync bf16 GEMM (NT): C[M,N] = A[M,K] * B[N,K]^T, both K-major (ld = K)
//   EPI=0 : C(bf16) = bf16(acc)
//   EPI=1 : C(bf16) = bf16( f32(Res) + f32(bf16(acc)) )
//   EPI=2 : C(f32)  = f32( bf16( f32(Res) + f32(bf16(acc)) ) )
// Batched over blockIdx.z: B += z*wstride, C += z*ostride.
// Block 128x128, BK=64 (32 barriers @ K=2048), 3-stage cp.async,
// ONE __syncthreads per K-tile. 8 warps (2M x 4N), warp 64x32.
// Single fragment set per k-step (round-14 proven: no reg headroom for
// fragment double-buffering at 64 acc regs). smem rows 144B, conflict-free.
// ===========================================================================
constexpr int BM = 128, BN = 128, BK = 64;
constexpr int NBUF   = 3;
constexpr int ROWB   = 144;                // 128B data + 16B pad
constexpr int ASTAGE = BM * ROWB;          // 18432
constexpr int BSTAGE = BN * ROWB;          // 18432
constexpr int AOFF   = 0;
constexpr int BOFF   = NBUF * ASTAGE;      // 55296
constexpr int SMEM_GEMM = NBUF * (ASTAGE + BSTAGE);   // 110592

template <int EPI>
__global__ __launch_bounds__(256, 2)
void gemm_mma(const __nv_bfloat16* __restrict__ A,
              const __nv_bfloat16* __restrict__ B,
              const __nv_bfloat16* __restrict__ Res,
              void* __restrict__ Cv,
              int K, int ldc, size_t wstride, size_t ostride) {
    extern __shared__ __align__(16) char ds[];
    const uint32_t sb = smem_u32(ds);

    const int tid  = threadIdx.x;
    const int wid  = tid >> 5;
    const int lane = tid & 31;
    const int bm = blockIdx.y * BM;
    const int bn = blockIdx.x * BN;
    const int wm = (wid & 1) * 64;         // warp M offset (2 warps over M)
    const int wn = (wid >> 1) * 32;        // warp N offset (4 warps over N)

    B += (size_t)blockIdx.z * wstride;

    // ---- tile loader: stage s <- K-tile t (BK=64 -> 8 chunks/row) --------
    auto load = [&](int t, int s) {
        const int k0 = t * BK;
        char* ab = ds + AOFF + s * ASTAGE;
        char* bb = ds + BOFF + s * BSTAGE;
#pragma unroll
        for (int v = 0; v < 4; v++) {                 // A: 1024 x 16B chunks
            int vi = tid + v * 256;
            int row = vi >> 3, ch = vi & 7;
            cp_async16(ab + row * ROWB + ch * 16,
                       A + (size_t)(bm + row) * K + k0 + ch * 8);
        }
#pragma unroll
        for (int v = 0; v < 4; v++) {                 // B: 1024 x 16B chunks
            int vi = tid + v * 256;
            int row = vi >> 3, ch = vi & 7;
            cp_async16(bb + row * ROWB + ch * 16,
                       B + (size_t)(bn + row) * K + k0 + ch * 8);
        }
        CP_COMMIT();
    };

    float acc[4][4][4];                               // [mi][nj][frag]
#pragma unroll
    for (int i = 0; i < 4; i++)
#pragma unroll
        for (int j = 0; j < 4; j++)
#pragma unroll
            for (int c = 0; c < 4; c++) acc[i][j][c] = 0.0f;

    const int nt = K / BK;                // 32 or 16
    load(0, 0);
    load(1, 1);

    for (int t = 0; t < nt; t++) {
        if (t + 1 < nt) { CP_WAIT_N(1); } else { CP_WAIT_N(0); }
        __syncthreads();   // tile t visible; all warps' compute(t-1) done

        if (t + 2 < nt) load(t + 2, (t + 2) % 3);

        const int buf = t % 3;
        const uint32_t aB = sb + AOFF + buf * ASTAGE;
        const uint32_t bB = sb + BOFF + buf * BSTAGE;

#pragma unroll
        for (int ks = 0; ks < 4; ks++) {              // four K=16 steps
            uint32_t aF[4][4], bF[2][4];
#pragma unroll
            for (int i = 0; i < 4; i++) {
                uint32_t addr = aB + (uint32_t)(wm + i * 16 + (lane & 15)) * ROWB
                              + ks * 32 + ((lane >> 4) << 4);
                LDSM4(aF[i], addr);
            }
#pragma unroll
            for (int p = 0; p < 2; p++) {
                uint32_t row = wn + p * 16 + ((lane & 7) | (((lane >> 4) & 1) << 3));
                uint32_t addr = bB + row * ROWB + ks * 32 + (((lane >> 3) & 1) << 4);
                LDSM4(bF[p], addr);
            }
#pragma unroll
            for (int i = 0; i < 4; i++)
#pragma unroll
                for (int j = 0; j < 4; j++)
                    MMA16816(acc[i][j], aF[i], &bF[j >> 1][(j & 1) * 2]);
        }
        // top-of-next-iteration barrier orders buffer reuse
    }

    // ---- fused epilogue (direct fragment-indexed stores) -----------------
    __nv_bfloat16* Cb = reinterpret_cast<__nv_bfloat16*>(Cv) + (size_t)blockIdx.z * ostride;
    float*         Cf = reinterpret_cast<float*>(Cv);
    const int er = lane >> 2;            // 0..7
    const int ec = (lane & 3) * 2;       // 0,2,4,6

#pragma unroll
    for (int i = 0; i < 4; i++) {
#pragma unroll
        for (int j = 0; j < 4; j++) {
            const int gcol = bn + wn + j * 8 + ec;
#pragma unroll
            for (int h = 0; h < 2; h++) {             // rows er and er+8
                const int grow = bm + wm + i * 16 + er + h * 8;
                const size_t base = (size_t)grow * ldc + gcol;
                float x0 = acc[i][j][2 * h], x1 = acc[i][j][2 * h + 1];
                __nv_bfloat162 t2 = __floats2bfloat162_rn(x0, x1);
                if constexpr (EPI == 0) {
                    *reinterpret_cast<__nv_bfloat162*>(Cb + base) = t2;
                } else {
                    __nv_bfloat162 r2 = *reinterpret_cast<const __nv_bfloat162*>(Res + base);
                    float ox = __bfloat162float(r2.x) + __bfloat162float(t2.x);
                    float oy = __bfloat162float(r2.y) + __bfloat162float(t2.y);
                    __nv_bfloat162 ob = __floats2bfloat162_rn(ox, oy);
                    if constexpr (EPI == 1) {
                        *reinterpret_cast<__nv_bfloat162*>(Cb + base) = ob;
                    } else {
                        float2 of;
                        of.x = __bfloat162float(ob.x);
                        of.y = __bfloat162float(ob.y);
                        *reinterpret_cast<float2*>(Cf + base) = of;
                    }
                }
            }
        }
    }
}

// ===========================================================================
// Input conversion / transposes
// ===========================================================================
__global__ void cvt_hidden_kernel(const float* __restrict__ s, int n4) {
    const float4* src = reinterpret_cast<const float4*>(s);
    __nv_bfloat162* dst = reinterpret_cast<__nv_bfloat162*>(g_s.hidden);
    for (int i = blockIdx.x * blockDim.x + threadIdx.x; i < n4;
         i += gridDim.x * blockDim.x) {
        float4 v = src[i];
        dst[2 * i]     = __floats2bfloat162_rn(v.x, v.y);
        dst[2 * i + 1] = __floats2bfloat162_rn(v.z, v.w);
    }
}

struct TPack { const float* s[7]; };

// wT[z][n*HID + k] = bf16(W[z][k*HID + n])
// 64x64 tiles, float4-vectorized loads, 16B-vector bf16 stores.
__global__ void transpose_w_kernel(TPack p) {
    __shared__ float tile[64][65];
    const float* src = p.s[blockIdx.z];
    __nv_bfloat16* dst = g_s.wT[blockIdx.z];
    const int tid = threadIdx.x;                    // 256 threads
    const int k0 = blockIdx.y * 64;                 // source row base (k)
    const int n0 = blockIdx.x * 64;                 // source col base (n)

#pragma unroll
    for (int v = 0; v < 4; v++) {
        int idx = tid + v * 256;
        int r = idx >> 4, c4 = idx & 15;
        float4 f = *reinterpret_cast<const float4*>(
            src + (size_t)(k0 + r) * HID + n0 + c4 * 4);
        tile[r][c4 * 4 + 0] = f.x;
        tile[r][c4 * 4 + 1] = f.y;
        tile[r][c4 * 4 + 2] = f.z;
        tile[r][c4 * 4 + 3] = f.w;
    }
    __syncthreads();

#pragma unroll
    for (int v = 0; v < 2; v++) {
        int idx = tid + v * 256;
        int n = idx >> 3, seg = idx & 7;
        __nv_bfloat162 o[4];
#pragma unroll
        for (int j = 0; j < 4; j++)
            o[j] = __floats2bfloat162_rn(tile[seg * 8 + 2 * j][n],
                                         tile[seg * 8 + 2 * j + 1][n]);
        *reinterpret_cast<uint4*>(dst + (size_t)(n0 + n) * HID + k0 + seg * 8) =
            *reinterpret_cast<uint4*>(o);
    }
}

// vT[h*AKEY + s] = v[s*HID + h]   (s < AKEY)
__global__ void transpose_v_kernel() {
    __shared__ __nv_bfloat16 tile[32][33];
    const int x  = blockIdx.x * 32 + threadIdx.x;   // h
    const int y0 = blockIdx.y * 32;                 // s base
#pragma unroll
    for (int j = 0; j < 32; j += 8)
        tile[threadIdx.y + j][threadIdx.x] =
            g_s.v[(size_t)(y0 + threadIdx.y + j) * HID + x];
    __syncthreads();
    const int h = blockIdx.x * 32 + threadIdx.y;
    const int s = y0 + threadIdx.x;
#pragma unroll
    for (int j = 0; j < 32; j += 8)
        g_s.vT[(size_t)(h + j) * AKEY + s] = tile[threadIdx.x][threadIdx.y + j];
}

// ===========================================================================
// Softmax (reference rounding) — shuffle reductions, 2 barriers
// ===========================================================================
__global__ void softmax_kernel(const __nv_bfloat16* __restrict__ sc,
                               __nv_bfloat16* __restrict__ pr) {
    const int row = blockIdx.x;
    const int tid = threadIdx.x;
    const int wid = tid >> 5;
    const int lane = tid & 31;
    const float scale = 0.022097086912079608f;  // 1/sqrt(2048)
    __shared__ float shm[8], shs[8];

    float x[4];
#pragma unroll
    for (int i = 0; i < 4; i++) {
        float vraw = __bfloat162float(sc[(size_t)row * AKEY + tid + i * 256]) * scale;
        x[i] = __bfloat162float(__float2bfloat16(vraw));
    }
    float m = fmaxf(fmaxf(x[0], x[1]), fmaxf(x[2], x[3]));
#pragma unroll
    for (int off = 16; off > 0; off >>= 1)
        m = fmaxf(m, __shfl_xor_sync(0xFFFFFFFFu, m, off));
    if (lane == 0) shm[wid] = m;
    __syncthreads();
    float mall = shm[0];
#pragma unroll
    for (int w = 1; w < 8; w++) mall = fmaxf(mall, shm[w]);

    float e[4]; float sum = 0.f;
#pragma unroll
    for (int i = 0; i < 4; i++) { e[i] = expf(x[i] - mall); sum += e[i]; }
#pragma unroll
    for (int off = 16; off > 0; off >>= 1)
        sum += __shfl_xor_sync(0xFFFFFFFFu, sum, off);
    if (lane == 0) shs[wid] = sum;
    __syncthreads();
    float tot = 0.f;
#pragma unroll
    for (int w = 0; w < 8; w++) tot += shs[w];

#pragma unroll
    for (int i = 0; i < 4; i++)
        pr[(size_t)row * AKEY + tid + i * 256] = __float2bfloat16(e[i] / tot);
}

// ===========================================================================
// gated = bf16( f32(bf16(gelu_tanh(f32(gate)))) * f32(up) )
// ===========================================================================
__global__ void gelu_mul_kernel(const __nv_bfloat16* __restrict__ g,
                                const __nv_bfloat16* __restrict__ u,
                                __nv_bfloat16* __restrict__ o, int n2) {
    for (int i = blockIdx.x * blockDim.x + threadIdx.x; i < n2;
         i += gridDim.x * blockDim.x) {
        __nv_bfloat162 gv = reinterpret_cast<const __nv_bfloat162*>(g)[i];
        __nv_bfloat162 uv = reinterpret_cast<const __nv_bfloat162*>(u)[i];
        float xs[2] = {__bfloat162float(gv.x), __bfloat162float(gv.y)};
        float us[2] = {__bfloat162float(uv.x), __bfloat162float(uv.y)};
        float os[2];
#pragma unroll
        for (int c = 0; c < 2; c++) {
            float x = xs[c];
            float t = tanhf(0.7978845608028654f * (x + 0.044715f * x * x * x));
            float act = 0.5f * x * (1.0f + t);
            float ab = __bfloat162float(__float2bfloat16(act));
            os[c] = ab * us[c];
        }
        reinterpret_cast<__nv_bfloat162*>(o)[i] = __floats2bfloat162_rn(os[0], os[1]);
    }
}

// ===========================================================================
// kernel_launch
// ===========================================================================
extern "C" void kernel_launch(void* const* d_in, const int* in_sizes, int n_in,
                              void* d_out, int out_size) {
    Scratch* S;
    cudaGetSymbolAddress((void**)&S, g_s);

    cudaFuncSetAttribute(gemm_mma<0>, cudaFuncAttributeMaxDynamicSharedMemorySize, SMEM_GEMM);
    cudaFuncSetAttribute(gemm_mma<1>, cudaFuncAttributeMaxDynamicSharedMemorySize, SMEM_GEMM);
    cudaFuncSetAttribute(gemm_mma<2>, cudaFuncAttributeMaxDynamicSharedMemorySize, SMEM_GEMM);

    // input order: hidden, q_proj, k_proj, v_proj, o_proj, gate_proj, up_proj, down_proj
    cvt_hidden_kernel<<<256, 256>>>((const float*)d_in[0], SEQ * HID / 4);
    TPack tp;
    for (int i = 0; i < 7; i++) tp.s[i] = (const float*)d_in[i + 1];
    transpose_w_kernel<<<dim3(32, 32, 7), 256>>>(tp);

    const size_t WS = (size_t)HID * HID;
    const size_t OS = (size_t)SEQ * HID;
    const dim3 blk(256);

    // q,k,v = hidden @ W^T  (batched z=3)
    gemm_mma<0><<<dim3(HID / BN, SEQ / BM, 3), blk, SMEM_GEMM>>>(
        S->hidden, S->wT[0], nullptr, S->q, HID, HID, WS, OS);

    // vT = v[:AKEY,:]^T
    transpose_v_kernel<<<dim3(HID / 32, AKEY / 32), dim3(32, 8)>>>();

    // scores = q @ k[:AKEY]^T  (NT natural)
    gemm_mma<0><<<dim3(AKEY / BN, SEQ / BM, 1), blk, SMEM_GEMM>>>(
        S->q, S->k, nullptr, S->scores, HID, AKEY, 0, 0);

    softmax_kernel<<<SEQ, 256>>>(S->scores, S->probs);

    // context = probs @ v[:AKEY]  (B = vT [HID][AKEY])
    gemm_mma<0><<<dim3(HID / BN, SEQ / BM, 1), blk, SMEM_GEMM>>>(
        S->probs, S->vT, nullptr, S->ctx, AKEY, HID, 0, 0);

    // post = bf16(f32(hidden) + f32(bf16(ctx @ o_proj)))
    gemm_mma<1><<<dim3(HID / BN, SEQ / BM, 1), blk, SMEM_GEMM>>>(
        S->ctx, S->wT[3], S->hidden, S->post, HID, HID, 0, 0);

    // gate,up = post @ {gate,up}^T  (batched z=2)
    gemm_mma<0><<<dim3(HID / BN, SEQ / BM, 2), blk, SMEM_GEMM>>>(
        S->post, S->wT[4], nullptr, S->gate, HID, HID, WS, OS);

    gelu_mul_kernel<<<2048, 256>>>(S->gate, S->up, S->gated, SEQ * HID / 2);

    // out(f32) = f32(bf16(f32(post) + f32(bf16(gated @ down^T))))
    gemm_mma<2><<<dim3(HID / BN, SEQ / BM, 1), blk, SMEM_GEMM>>>(
        S->gated, S->wT[6], S->post, d_out, HID, HID, 0, 0);
}